// round 12
// baseline (speedup 1.0000x reference)
#include <cuda_runtime.h>
#include <cstdint>

// ---- smem layout (bytes) ----
#define FP      544                  // feat row pitch: 136 floats (128 px + pad)
#define FBUF    8704                 // one tensor chunk: 16 k-rows * 544
#define FSTAGE  17408                // per-stage feat: 2 tensors
#define FOFF    0                    // 3 stages * 17408 = 52224
#define WPITCH  80                   // weight row pitch: 20 floats (16 k + pad)
#define WBUF    12800                // 160 o-rows * 80
#define WOFF    52224                // 3 stages * 12800 = 38400
#define MBAR_OFF 90624               // 3 x 8B mbarriers
#define SMEM_TOTAL 90688             // x2 CTA = 181376 <= 227KB
#define SP 153                       // epilogue stage pitch (floats); 128*153*4 = 78336 < MBAR_OFF

struct Params {
    const float* clsF[3]; const float* regF[3];
    const float* ow[3]; const float* ob[3];
    const float* cw[3]; const float* cb[3];
    const float* rw[3]; const float* rb[3];
};

extern __shared__ char smch[];

__device__ __forceinline__ uint32_t smu32(const void* p) {
    uint32_t a;
    asm("{ .reg .u64 t; cvta.to.shared.u64 t, %1; cvt.u32.u64 %0, t; }" : "=r"(a) : "l"(p));
    return a;
}
__device__ __forceinline__ uint32_t lds1(uint32_t a) {
    uint32_t v;
    asm volatile("ld.shared.b32 %0, [%1];" : "=r"(v) : "r"(a));
    return v;
}
__device__ __forceinline__ void mma_tf32(float* d, const uint32_t* a, uint32_t b0, uint32_t b1) {
    asm volatile("mma.sync.aligned.m16n8k8.row.col.f32.tf32.tf32.f32 "
                 "{%0,%1,%2,%3}, {%4,%5,%6,%7}, {%8,%9}, {%0,%1,%2,%3};"
                 : "+f"(d[0]), "+f"(d[1]), "+f"(d[2]), "+f"(d[3])
                 : "r"(a[0]), "r"(a[1]), "r"(a[2]), "r"(a[3]), "r"(b0), "r"(b1));
}
__device__ __forceinline__ void mbar_init(uint32_t a, uint32_t cnt) {
    asm volatile("mbarrier.init.shared.b64 [%0], %1;" :: "r"(a), "r"(cnt) : "memory");
}
__device__ __forceinline__ void mbar_expect_tx(uint32_t a, uint32_t tx) {
    asm volatile("mbarrier.arrive.expect_tx.shared.b64 _, [%0], %1;" :: "r"(a), "r"(tx) : "memory");
}
__device__ __forceinline__ void mbar_wait(uint32_t a, uint32_t par) {
    asm volatile("{\n\t.reg .pred P;\n\tLW%=:\n\t"
                 "mbarrier.try_wait.parity.shared.b64 P, [%0], %1;\n\t"
                 "@!P bra LW%=;\n\t}" :: "r"(a), "r"(par) : "memory");
}
__device__ __forceinline__ void bulk_cp(uint32_t dst, const float* src, uint32_t bytes, uint32_t mbar) {
    asm volatile("cp.async.bulk.shared::cluster.global.mbarrier::complete_tx::bytes "
                 "[%0], [%1], %2, [%3];"
                 :: "r"(dst), "l"(src), "r"(bytes), "r"(mbar) : "memory");
}

// distributed bulk staging: threads 0..31 feat rows, 32..176 weight rows
__device__ __forceinline__ void issue_chunk(int c, int st,
        const float* clsF, const float* regF,
        const float* cw, const float* rw, const float* ow,
        uint32_t sb, int M, int m0, uint32_t fbytes, int t)
{
    const uint32_t mbar = sb + MBAR_OFF + st * 8;
    if (t == 0)
        mbar_expect_tx(mbar, 32u * fbytes + 145u * 64u);
    if (t < 32) {
        int tensor = t >> 4, r = t & 15;
        const float* src = (tensor ? regF : clsF) + (size_t)(c * 16 + r) * M + m0;
        uint32_t dst = sb + FOFF + st * FSTAGE + tensor * FBUF + r * FP;
        bulk_cp(dst, src, fbytes, mbar);
    } else if (t < 32 + 145) {
        int o = t - 32;
        const float* src = (o < 80)  ? (cw + o * 256 + c * 16)
                         : (o < 144) ? (rw + (o - 80) * 256 + c * 16)
                                     : (ow + c * 16);
        uint32_t dst = sb + WOFF + st * WBUF + o * WPITCH;
        bulk_cp(dst, src, 64u, mbar);
    }
}

__global__ __launch_bounds__(256, 2) void pred_tf32_kernel(Params P, float* __restrict__ out)
{
    const int t = threadIdx.x, lane = t & 31, wid = t >> 5;
    const int wo = wid >> 1, wpx = wid & 1;     // 4 o-groups x 2 px-groups
    const int tb = blockIdx.x, b = blockIdx.y;

    int l, tile;
    if (tb < 50)      { l = 0; tile = tb; }
    else if (tb < 63) { l = 1; tile = tb - 50; }
    else              { l = 2; tile = tb - 63; }
    const int   Ms[3]    = {6400, 1600, 400};
    const int   Wg[3]    = {80, 40, 20};
    const int   moffs[3] = {0, 6400, 8000};
    const float strs[3]  = {8.f, 16.f, 32.f};
    const int M = Ms[l], W = Wg[l], moff = moffs[l];
    const float stride = strs[l];
    const int m0 = tile * 128;
    const int mvalid = min(128, M - m0);
    const uint32_t fbytes = (uint32_t)mvalid * 4u;   // always a 16B multiple (mvalid in {128,64,16})

    const float* clsF = P.clsF[l] + (size_t)b * 256 * M;
    const float* regF = P.regF[l] + (size_t)b * 256 * M;
    const float* cw = P.cw[l];
    const float* rw = P.rw[l];
    const float* ow = P.ow[l];
    const uint32_t sb = smu32(smch);

    // prologue: mbarriers, zero weight pad rows (o=145..159, all stages), then stage 0,1
    if (t < 3) mbar_init(sb + MBAR_OFF + t * 8, 1);
    for (int i = t; i < 3 * 15 * 20; i += 256) {
        int st = i / 300, r = i % 300;
        int o = 145 + r / 20, q = r % 20;
        *(float*)(smch + WOFF + st * WBUF + o * WPITCH + q * 4) = 0.f;
    }
    __syncthreads();
    issue_chunk(0, 0, clsF, regF, cw, rw, ow, sb, M, m0, fbytes, t);
    issue_chunk(1, 1, clsF, regF, cw, rw, ow, sb, M, m0, fbytes, t);

    float acc[4][5][4];
    #pragma unroll
    for (int mt = 0; mt < 4; mt++)
        #pragma unroll
        for (int nt = 0; nt < 5; nt++)
            #pragma unroll
            for (int j = 0; j < 4; j++) acc[mt][nt][j] = 0.f;

    // per-thread invariant smem offsets
    const uint32_t abase = sb + FOFF + (wo >> 1) * FBUF
                         + (uint32_t)(lane & 3) * FP
                         + (uint32_t)(wpx * 64 + (lane >> 2)) * 4;
    const uint32_t bbase = sb + WOFF
                         + (uint32_t)(wo * 40 + (lane >> 2)) * WPITCH
                         + (uint32_t)(lane & 3) * 4;

    int st = 0, ist = 2;
    #pragma unroll 1
    for (int c = 0; c < 16; c++) {
        __syncthreads();   // all warps done computing on stage ist (chunk c-1)

        if (c + 2 < 16)
            issue_chunk(c + 2, ist, clsF, regF, cw, rw, ow, sb, M, m0, fbytes, t);

        // wait for stage st data (use index c/3, parity (c/3)&1)
        mbar_wait(sb + MBAR_OFF + st * 8, (uint32_t)((c / 3) & 1));

        const uint32_t fb = abase + st * FSTAGE;
        const uint32_t wb = bbase + st * WBUF;
        #pragma unroll
        for (int s = 0; s < 2; s++) {
            uint32_t a[4][4];
            #pragma unroll
            for (int mt = 0; mt < 4; mt++) {
                uint32_t ab = fb + s * (8 * FP) + mt * 64;
                a[mt][0] = lds1(ab);
                a[mt][1] = lds1(ab + 32);
                a[mt][2] = lds1(ab + 4 * FP);
                a[mt][3] = lds1(ab + 4 * FP + 32);
            }
            #pragma unroll
            for (int nt = 0; nt < 5; nt++) {
                uint32_t w2 = wb + s * 32 + nt * (8 * WPITCH);
                uint32_t b0 = lds1(w2), b1 = lds1(w2 + 16);
                #pragma unroll
                for (int mt = 0; mt < 4; mt++) mma_tf32(acc[mt][nt], a[mt], b0, b1);
            }
        }
        st  = (st  == 2) ? 0 : st  + 1;
        ist = (ist == 2) ? 0 : ist + 1;
    }
    __syncthreads();   // last compute done everywhere before stage alias reuse

    // ---- epilogue: single pass over all 128 px (stage aliases mainloop smem) ----
    const float* cb = P.cb[l];
    const float* rb = P.rb[l];
    const float* ob = P.ob[l];
    float* stg = reinterpret_cast<float*>(smch);

    #pragma unroll
    for (int mt = 0; mt < 4; mt++)
        #pragma unroll
        for (int nt = 0; nt < 5; nt++)
            #pragma unroll
            for (int j = 0; j < 4; j++) {
                int o = wo * 40 + nt * 8 + (lane & 3) * 2 + (j & 1);
                if (o <= 144) {
                    int px = wpx * 64 + mt * 16 + (lane >> 2) + (j >> 1) * 8;
                    float bias = (o < 80)  ? __ldg(&cb[o])
                               : (o < 144) ? __ldg(&rb[o - 80])
                                           : __ldg(ob);
                    int ch = (o == 144) ? 0 : o + 1;
                    stg[px * SP + ch] = acc[mt][nt][j] + bias;
                }
            }
    __syncthreads();

    // DFL decode + box: 512 tasks, 2 per thread; max-free softmax (bounded logits)
    #pragma unroll
    for (int it = 0; it < 2; it++) {
        int task = t + it * 256;
        int m = task >> 2, f = task & 3;
        const float* row = &stg[m * SP + 81 + 16 * f];
        float se = 0.f, sw = 0.f;
        #pragma unroll
        for (int i = 0; i < 16; i++) {
            float ev = __expf(row[i]);
            se += ev;
            sw = fmaf(ev, (float)i, sw);
        }
        float d = (sw / se) * (16.0f / 15.0f);   // proj[i] = i * 16/15
        int mg = m0 + m;
        int hh = mg / W, ww = mg - hh * W;
        float ax = ((float)ww + 0.5f) * stride;
        float ay = ((float)hh + 0.5f) * stride;
        float ds = d * stride;
        float v = (f == 0) ? (ax - ds) : (f == 1) ? (ay - ds)
                : (f == 2) ? (ax + ds) : (ay + ds);
        stg[m * SP + 145 + f] = v;
    }
    __syncthreads();

    // div-free coalesced store: warp owns pixels wid, wid+8, ...; lanes stride channels
    {
        float* outp = out + ((size_t)b * 8400 + moff + m0) * 149;
        for (int m = wid; m < mvalid; m += 8) {
            const float* srow = stg + m * SP;
            float* drow = outp + m * 149;
            #pragma unroll
            for (int c2 = lane; c2 < 149; c2 += 32)
                drow[c2] = srow[c2];
        }
    }
}

extern "C" void kernel_launch(void* const* d_in, const int* in_sizes, int n_in,
                              void* d_out, int out_size)
{
    Params P;
    if (in_sizes[1] == in_sizes[0]) {       // dict order cls0,reg0,cls1,reg1,cls2,reg2
        P.clsF[0] = (const float*)d_in[0]; P.regF[0] = (const float*)d_in[1];
        P.clsF[1] = (const float*)d_in[2]; P.regF[1] = (const float*)d_in[3];
        P.clsF[2] = (const float*)d_in[4]; P.regF[2] = (const float*)d_in[5];
    } else {                                // signature order cls0,cls1,cls2,reg0,reg1,reg2
        P.clsF[0] = (const float*)d_in[0]; P.regF[0] = (const float*)d_in[3];
        P.clsF[1] = (const float*)d_in[1]; P.regF[1] = (const float*)d_in[4];
        P.clsF[2] = (const float*)d_in[2]; P.regF[2] = (const float*)d_in[5];
    }
    for (int l = 0; l < 3; l++) {
        P.ow[l] = (const float*)d_in[6  + 6 * l];
        P.ob[l] = (const float*)d_in[7  + 6 * l];
        P.cw[l] = (const float*)d_in[8  + 6 * l];
        P.cb[l] = (const float*)d_in[9  + 6 * l];
        P.rw[l] = (const float*)d_in[10 + 6 * l];
        P.rb[l] = (const float*)d_in[11 + 6 * l];
    }
    int B = in_sizes[0] / (256 * 6400);

    static int configured = 0;
    if (!configured) {
        cudaFuncSetAttribute(pred_tf32_kernel, cudaFuncAttributeMaxDynamicSharedMemorySize, SMEM_TOTAL);
        configured = 1;
    }
    dim3 grid(67, B);                       // 50 + 13 + 4 tiles per batch
    pred_tf32_kernel<<<grid, 256, SMEM_TOTAL>>>(P, (float*)d_out);
}

// round 13
// speedup vs baseline: 1.0970x; 1.0970x over previous
#include <cuda_runtime.h>
#include <cstdint>

// ---- smem layout (bytes) ----
#define FP      544                  // feat row pitch: 136 floats (128 px + pad)
#define FBUF    8704                 // one tensor chunk: 16 k-rows * 544
#define FSTAGE  17408                // per-stage feat: 2 tensors
#define FOFF    0                    // 3 stages * 17408 = 52224
#define WPITCH  80                   // weight row pitch: 20 floats (16 k + pad)
#define WBUF    12800                // 160 o-rows * 80
#define WOFF    52224                // 3 stages * 12800 = 38400
#define SMEM_TOTAL 90624             // 52224 + 38400 ; x2 CTA = 181248 <= 227KB
#define SP 153                       // epilogue stage pitch (floats); 128*153*4 = 78336 <= 90624

struct Params {
    const float* clsF[3]; const float* regF[3];
    const float* ow[3]; const float* ob[3];
    const float* cw[3]; const float* cb[3];
    const float* rw[3]; const float* rb[3];
};

extern __shared__ char smch[];

__device__ __forceinline__ uint32_t smu32(const void* p) {
    uint32_t a;
    asm("{ .reg .u64 t; cvta.to.shared.u64 t, %1; cvt.u32.u64 %0, t; }" : "=r"(a) : "l"(p));
    return a;
}
__device__ __forceinline__ uint2 lds2(uint32_t a) {
    uint2 v;
    asm volatile("ld.shared.v2.b32 {%0,%1}, [%2];" : "=r"(v.x), "=r"(v.y) : "r"(a));
    return v;
}
__device__ __forceinline__ void mma_tf32(float* d, const uint32_t* a, uint32_t b0, uint32_t b1) {
    asm volatile("mma.sync.aligned.m16n8k8.row.col.f32.tf32.tf32.f32 "
                 "{%0,%1,%2,%3}, {%4,%5,%6,%7}, {%8,%9}, {%0,%1,%2,%3};"
                 : "+f"(d[0]), "+f"(d[1]), "+f"(d[2]), "+f"(d[3])
                 : "r"(a[0]), "r"(a[1]), "r"(a[2]), "r"(a[3]), "r"(b0), "r"(b1));
}
__device__ __forceinline__ void cpa_cg(uint32_t dst, const float* src, int sz) {
    asm volatile("cp.async.cg.shared.global [%0], [%1], 16, %2;"
                 :: "r"(dst), "l"(src), "r"(sz) : "memory");
}
__device__ __forceinline__ void cpa_ca(uint32_t dst, const float* src, int sz) {
    asm volatile("cp.async.ca.shared.global [%0], [%1], 16, %2;"
                 :: "r"(dst), "l"(src), "r"(sz) : "memory");
}

__device__ __forceinline__ void issue_chunk(int c, int st,
        const float* clsF, const float* regF,
        const float* cw, const float* rw, const float* ow,
        uint32_t sb, int M, int m0, int mvalid, int t)
{
    // features: 2 tensors x 16 k-rows x 32 quads of 16B
    #pragma unroll
    for (int it = 0; it < 4; it++) {
        int i = t + it * 256;
        int tensor = i >> 9, r = (i >> 5) & 15, q = i & 31;
        const float* src = (tensor ? regF : clsF) + (size_t)(c * 16 + r) * M + m0 + q * 4;
        uint32_t dst = sb + FOFF + st * FSTAGE + tensor * FBUF + r * FP + q * 16;
        cpa_cg(dst, src, (q * 4 < mvalid) ? 16 : 0);
    }
    // weights: 160 o-rows x 4 quads of 16B (rows 145..159 zero-filled)
    #pragma unroll
    for (int it = 0; it < 3; it++) {
        int i = t + it * 256;
        if (i < 640) {
            int o = i >> 2, q = i & 3;
            const float* src = ow;
            int sz = 0;
            if (o < 80)        { src = cw + o * 256 + c * 16 + q * 4; sz = 16; }
            else if (o < 144)  { src = rw + (o - 80) * 256 + c * 16 + q * 4; sz = 16; }
            else if (o == 144) { src = ow + c * 16 + q * 4; sz = 16; }
            cpa_ca(sb + WOFF + st * WBUF + o * WPITCH + q * 16, src, sz);
        }
    }
    asm volatile("cp.async.commit_group;" ::: "memory");
}

__global__ __launch_bounds__(256, 2) void pred_tf32_kernel(Params P, float* __restrict__ out)
{
    const int t = threadIdx.x, lane = t & 31, wid = t >> 5;
    const int wo = wid >> 1, wpx = wid & 1;     // 4 o-groups x 2 px-groups
    const int tb = blockIdx.x, b = blockIdx.y;

    int l, tile;
    if (tb < 50)      { l = 0; tile = tb; }
    else if (tb < 63) { l = 1; tile = tb - 50; }
    else              { l = 2; tile = tb - 63; }
    const int   Ms[3]    = {6400, 1600, 400};
    const int   Wg[3]    = {80, 40, 20};
    const int   moffs[3] = {0, 6400, 8000};
    const float strs[3]  = {8.f, 16.f, 32.f};
    const int M = Ms[l], W = Wg[l], moff = moffs[l];
    const float stride = strs[l];
    const int m0 = tile * 128;
    const int mvalid = min(128, M - m0);

    const float* clsF = P.clsF[l] + (size_t)b * 256 * M;
    const float* regF = P.regF[l] + (size_t)b * 256 * M;
    const float* cw = P.cw[l];
    const float* rw = P.rw[l];
    const float* ow = P.ow[l];
    const uint32_t sb = smu32(smch);

    // prologue: fill 2 of 3 pipeline stages
    issue_chunk(0, 0, clsF, regF, cw, rw, ow, sb, M, m0, mvalid, t);
    issue_chunk(1, 1, clsF, regF, cw, rw, ow, sb, M, m0, mvalid, t);

    float acc[4][5][4];
    #pragma unroll
    for (int mt = 0; mt < 4; mt++)
        #pragma unroll
        for (int nt = 0; nt < 5; nt++)
            #pragma unroll
            for (int j = 0; j < 4; j++) acc[mt][nt][j] = 0.f;

    // Paired-index mappings make all fragment loads 64-bit:
    //  logical MMA col kappa   -> global k rows 2*kappa, 2*kappa+1 (A rows / B words adjacent)
    //  logical MMA row r / r+8 -> global px   2r, 2r+1            (A words adjacent)
    // k is a contraction index and px is re-inverted in the epilogue, so math is unchanged.
    const uint32_t abase = sb + FOFF + (wo >> 1) * FBUF
                         + (uint32_t)(lane & 3) * (2 * FP)
                         + (uint32_t)(wpx * 64 + (lane >> 2) * 2) * 4;
    const uint32_t bbase = sb + WOFF
                         + (uint32_t)(wo * 40 + (lane >> 2)) * WPITCH
                         + (uint32_t)(lane & 3) * 8;

    int st = 0, ist = 2;
    #pragma unroll 1
    for (int c = 0; c < 16; c++) {
        // chunk c resident once <=1 newer group outstanding (empty tail commits
        // keep the group numbering uniform through the last iterations)
        asm volatile("cp.async.wait_group 1;" ::: "memory");
        __syncthreads();   // publishes stage st to all warps; frees stage ist

        if (c + 2 < 16)
            issue_chunk(c + 2, ist, clsF, regF, cw, rw, ow, sb, M, m0, mvalid, t);
        else
            asm volatile("cp.async.commit_group;" ::: "memory");

        const uint32_t fb = abase + st * FSTAGE;
        const uint32_t wb = bbase + st * WBUF;
        #pragma unroll
        for (int s = 0; s < 2; s++) {
            uint32_t a[4][4];
            #pragma unroll
            for (int mt = 0; mt < 4; mt++) {
                uint32_t ab = fb + s * (8 * FP) + mt * 64;
                uint2 lo = lds2(ab);        // a0 (px 2r, k 2kap), a1 (px 2r+1)
                uint2 hi = lds2(ab + FP);   // a2 (px 2r, k 2kap+1), a3 (px 2r+1)
                a[mt][0] = lo.x; a[mt][1] = lo.y;
                a[mt][2] = hi.x; a[mt][3] = hi.y;
            }
            #pragma unroll
            for (int nt = 0; nt < 5; nt++) {
                uint2 bv = lds2(wb + s * 32 + nt * (8 * WPITCH));  // b0 (k 2kap), b1 (k 2kap+1)
                #pragma unroll
                for (int mt = 0; mt < 4; mt++) mma_tf32(acc[mt][nt], a[mt], bv.x, bv.y);
            }
        }
        st  = (st  == 2) ? 0 : st  + 1;
        ist = (ist == 2) ? 0 : ist + 1;
    }
    __syncthreads();   // last compute done everywhere before stage alias reuse

    // ---- epilogue: single pass over all 128 px (stage aliases all mainloop smem) ----
    const float* cb = P.cb[l];
    const float* rb = P.rb[l];
    const float* ob = P.ob[l];
    float* stg = reinterpret_cast<float*>(smch);

    #pragma unroll
    for (int mt = 0; mt < 4; mt++)
        #pragma unroll
        for (int nt = 0; nt < 5; nt++)
            #pragma unroll
            for (int j = 0; j < 4; j++) {
                int o = wo * 40 + nt * 8 + (lane & 3) * 2 + (j & 1);
                if (o <= 144) {
                    // inverse px mapping: logical row r/r+8 -> global px 2r/2r+1
                    int px = wpx * 64 + mt * 16 + (lane >> 2) * 2 + (j >> 1);
                    float bias = (o < 80)  ? __ldg(&cb[o])
                               : (o < 144) ? __ldg(&rb[o - 80])
                                           : __ldg(ob);
                    int ch = (o == 144) ? 0 : o + 1;
                    stg[px * SP + ch] = acc[mt][nt][j] + bias;
                }
            }
    __syncthreads();

    // DFL decode + box: 512 tasks, 2 per thread; max-free softmax (bounded logits)
    #pragma unroll
    for (int it = 0; it < 2; it++) {
        int task = t + it * 256;
        int m = task >> 2, f = task & 3;
        const float* row = &stg[m * SP + 81 + 16 * f];
        float se = 0.f, sw = 0.f;
        #pragma unroll
        for (int i = 0; i < 16; i++) {
            float ev = __expf(row[i]);
            se += ev;
            sw = fmaf(ev, (float)i, sw);
        }
        float d = (sw / se) * (16.0f / 15.0f);   // proj[i] = i * 16/15
        int mg = m0 + m;
        int hh = mg / W, ww = mg - hh * W;
        float ax = ((float)ww + 0.5f) * stride;
        float ay = ((float)hh + 0.5f) * stride;
        float ds = d * stride;
        float v = (f == 0) ? (ax - ds) : (f == 1) ? (ay - ds)
                : (f == 2) ? (ax + ds) : (ay + ds);
        stg[m * SP + 145 + f] = v;
    }
    __syncthreads();

    // div-free coalesced store: warp owns pixels wid, wid+8, ...; lanes stride channels
    {
        float* outp = out + ((size_t)b * 8400 + moff + m0) * 149;
        for (int m = wid; m < mvalid; m += 8) {
            const float* srow = stg + m * SP;
            float* drow = outp + m * 149;
            #pragma unroll
            for (int c2 = lane; c2 < 149; c2 += 32)
                drow[c2] = srow[c2];
        }
    }
}

extern "C" void kernel_launch(void* const* d_in, const int* in_sizes, int n_in,
                              void* d_out, int out_size)
{
    Params P;
    if (in_sizes[1] == in_sizes[0]) {       // dict order cls0,reg0,cls1,reg1,cls2,reg2
        P.clsF[0] = (const float*)d_in[0]; P.regF[0] = (const float*)d_in[1];
        P.clsF[1] = (const float*)d_in[2]; P.regF[1] = (const float*)d_in[3];
        P.clsF[2] = (const float*)d_in[4]; P.regF[2] = (const float*)d_in[5];
    } else {                                // signature order cls0,cls1,cls2,reg0,reg1,reg2
        P.clsF[0] = (const float*)d_in[0]; P.regF[0] = (const float*)d_in[3];
        P.clsF[1] = (const float*)d_in[1]; P.regF[1] = (const float*)d_in[4];
        P.clsF[2] = (const float*)d_in[2]; P.regF[2] = (const float*)d_in[5];
    }
    for (int l = 0; l < 3; l++) {
        P.ow[l] = (const float*)d_in[6  + 6 * l];
        P.ob[l] = (const float*)d_in[7  + 6 * l];
        P.cw[l] = (const float*)d_in[8  + 6 * l];
        P.cb[l] = (const float*)d_in[9  + 6 * l];
        P.rw[l] = (const float*)d_in[10 + 6 * l];
        P.rb[l] = (const float*)d_in[11 + 6 * l];
    }
    int B = in_sizes[0] / (256 * 6400);

    static int configured = 0;
    if (!configured) {
        cudaFuncSetAttribute(pred_tf32_kernel, cudaFuncAttributeMaxDynamicSharedMemorySize, SMEM_TOTAL);
        configured = 1;
    }
    dim3 grid(67, B);                       // 50 + 13 + 4 tiles per batch
    pred_tf32_kernel<<<grid, 256, SMEM_TOTAL>>>(P, (float*)d_out);
}

// round 14
// speedup vs baseline: 1.2482x; 1.1378x over previous
#include <cuda_runtime.h>
#include <cstdint>

// ---- smem layout (bytes) ----
#define FP      544                  // feat row pitch: 136 floats (128 px + pad)
#define FBUF    8704                 // one chunk: 16 k-rows * 544 (single tensor)
#define FOFF    0                    // 3 stages * 8704 = 26112
#define WPITCH  80                   // weight row pitch: 20 floats (16 k + pad)
#define WBUF    6400                 // 80 o-rows * 80
#define WOFF    26112                // 3 stages * 6400 = 19200
#define SMEM_TOTAL 45312             // x3 CTA = 135936 <= 227KB
#define SP2 81                       // epilogue stage pitch (floats); 128*81*4 = 41472 <= 45312

struct Params {
    const float* clsF[3]; const float* regF[3];
    const float* ow[3]; const float* ob[3];
    const float* cw[3]; const float* cb[3];
    const float* rw[3]; const float* rb[3];
};

extern __shared__ char smch[];

__device__ __forceinline__ uint32_t smu32(const void* p) {
    uint32_t a;
    asm("{ .reg .u64 t; cvta.to.shared.u64 t, %1; cvt.u32.u64 %0, t; }" : "=r"(a) : "l"(p));
    return a;
}
__device__ __forceinline__ uint32_t lds1(uint32_t a) {
    uint32_t v;
    asm volatile("ld.shared.b32 %0, [%1];" : "=r"(v) : "r"(a));
    return v;
}
__device__ __forceinline__ void mma_tf32(float* d, const uint32_t* a, uint32_t b0, uint32_t b1) {
    asm volatile("mma.sync.aligned.m16n8k8.row.col.f32.tf32.tf32.f32 "
                 "{%0,%1,%2,%3}, {%4,%5,%6,%7}, {%8,%9}, {%0,%1,%2,%3};"
                 : "+f"(d[0]), "+f"(d[1]), "+f"(d[2]), "+f"(d[3])
                 : "r"(a[0]), "r"(a[1]), "r"(a[2]), "r"(a[3]), "r"(b0), "r"(b1));
}
__device__ __forceinline__ void cpa_cg(uint32_t dst, const float* src, int sz) {
    asm volatile("cp.async.cg.shared.global [%0], [%1], 16, %2;"
                 :: "r"(dst), "l"(src), "r"(sz) : "memory");
}
__device__ __forceinline__ void cpa_ca(uint32_t dst, const float* src, int sz) {
    asm volatile("cp.async.ca.shared.global [%0], [%1], 16, %2;"
                 :: "r"(dst), "l"(src), "r"(sz) : "memory");
}

// Stage one k16 chunk: single feature tensor + this flavor's weight rows.
__device__ __forceinline__ void issue_chunk(int c, int st,
        const float* feat, const float* w0, const float* ow, int nwrows,
        uint32_t sb, int M, int m0, int mvalid, int t)
{
    // features: 16 k-rows x 32 quads of 16B
    #pragma unroll
    for (int it = 0; it < 2; it++) {
        int i = t + it * 256;
        int r = i >> 5, q = i & 31;
        const float* src = feat + (size_t)(c * 16 + r) * M + m0 + q * 4;
        uint32_t dst = sb + FOFF + st * FBUF + r * FP + q * 16;
        cpa_cg(dst, src, (q * 4 < mvalid) ? 16 : 0);
    }
    // weights: nwrows o-rows x 4 quads of 16B (w0 rows, last row may be obj)
    #pragma unroll
    for (int it = 0; it < 2; it++) {
        int i = t + it * 256;
        if (i < nwrows * 4) {
            int o = i >> 2, q = i & 3;
            const float* src = (o < 64 || nwrows == 80) ? (w0 + o * 256 + c * 16 + q * 4)
                                                        : (ow + c * 16 + q * 4);
            cpa_ca(sb + WOFF + st * WBUF + o * WPITCH + q * 16, src, 16);
        }
    }
    asm volatile("cp.async.commit_group;" ::: "memory");
}

__global__ __launch_bounds__(256, 3) void pred_tf32_kernel(Params P, float* __restrict__ out)
{
    const int t = threadIdx.x, lane = t & 31, wid = t >> 5;
    const int wo = wid >> 2, wpx = wid & 3;     // 2 o-groups (40) x 4 px-groups (32)
    const int tb = blockIdx.x, b = blockIdx.y;
    const int flavor = blockIdx.z;              // 0 = cls GEMM, 1 = reg+obj GEMM (+DFL)

    int l, tile;
    if (tb < 50)      { l = 0; tile = tb; }
    else if (tb < 63) { l = 1; tile = tb - 50; }
    else              { l = 2; tile = tb - 63; }
    const int   Ms[3]    = {6400, 1600, 400};
    const int   Wg[3]    = {80, 40, 20};
    const int   moffs[3] = {0, 6400, 8000};
    const float strs[3]  = {8.f, 16.f, 32.f};
    const int M = Ms[l], W = Wg[l], moff = moffs[l];
    const float stride = strs[l];
    const int m0 = tile * 128;
    const int mvalid = min(128, M - m0);

    const float* feat = (flavor ? P.regF[l] : P.clsF[l]) + (size_t)b * 256 * M;
    const float* w0   = flavor ? P.rw[l] : P.cw[l];
    const float* ow   = P.ow[l];
    const int nwrows  = flavor ? 65 : 80;
    const uint32_t sb = smu32(smch);

    // prologue: zero weight pad rows (flavor1: o=65..79, all stages), fill 2 stages
    if (flavor) {
        for (int i = t; i < 3 * 15 * 20; i += 256) {
            int st = i / 300, r = i % 300;
            int o = 65 + r / 20, q = r % 20;
            *(float*)(smch + WOFF + st * WBUF + o * WPITCH + q * 4) = 0.f;
        }
        __syncthreads();
    }
    issue_chunk(0, 0, feat, w0, ow, nwrows, sb, M, m0, mvalid, t);
    issue_chunk(1, 1, feat, w0, ow, nwrows, sb, M, m0, mvalid, t);

    float acc[2][5][4];
    #pragma unroll
    for (int mt = 0; mt < 2; mt++)
        #pragma unroll
        for (int nt = 0; nt < 5; nt++)
            #pragma unroll
            for (int j = 0; j < 4; j++) acc[mt][nt][j] = 0.f;

    // per-thread invariant smem offsets
    const uint32_t abase = sb + FOFF
                         + (uint32_t)(lane & 3) * FP
                         + (uint32_t)(wpx * 32 + (lane >> 2)) * 4;
    const uint32_t bbase = sb + WOFF
                         + (uint32_t)(wo * 40 + (lane >> 2)) * WPITCH
                         + (uint32_t)(lane & 3) * 4;

    int st = 0, ist = 2;
    #pragma unroll 1
    for (int c = 0; c < 16; c++) {
        asm volatile("cp.async.wait_group 1;" ::: "memory");
        __syncthreads();   // publishes stage st to all warps; frees stage ist

        if (c + 2 < 16)
            issue_chunk(c + 2, ist, feat, w0, ow, nwrows, sb, M, m0, mvalid, t);
        else
            asm volatile("cp.async.commit_group;" ::: "memory");

        const uint32_t fb = abase + st * FBUF;
        const uint32_t wb = bbase + st * WBUF;
        #pragma unroll
        for (int s = 0; s < 2; s++) {
            uint32_t a[2][4];
            #pragma unroll
            for (int mt = 0; mt < 2; mt++) {
                uint32_t ab = fb + s * (8 * FP) + mt * 64;
                a[mt][0] = lds1(ab);
                a[mt][1] = lds1(ab + 32);
                a[mt][2] = lds1(ab + 4 * FP);
                a[mt][3] = lds1(ab + 4 * FP + 32);
            }
            #pragma unroll
            for (int nt = 0; nt < 5; nt++) {
                uint32_t w2 = wb + s * 32 + nt * (8 * WPITCH);
                uint32_t b0 = lds1(w2), b1 = lds1(w2 + 16);
                #pragma unroll
                for (int mt = 0; mt < 2; mt++) mma_tf32(acc[mt][nt], a[mt], b0, b1);
            }
        }
        st  = (st  == 2) ? 0 : st  + 1;
        ist = (ist == 2) ? 0 : ist + 1;
    }
    __syncthreads();   // last compute done everywhere before stage alias reuse

    // ---- epilogue (stage aliases all mainloop smem; pitch SP2) ----
    float* stg = reinterpret_cast<float*>(smch);
    {
        const float* cb = P.cb[l];
        const float* rb = P.rb[l];
        const float* ob = P.ob[l];
        #pragma unroll
        for (int mt = 0; mt < 2; mt++)
            #pragma unroll
            for (int nt = 0; nt < 5; nt++)
                #pragma unroll
                for (int j = 0; j < 4; j++) {
                    int o = wo * 40 + nt * 8 + (lane & 3) * 2 + (j & 1);
                    int px = wpx * 32 + mt * 16 + (lane >> 2) + (j >> 1) * 8;
                    if (flavor == 0) {
                        // stage col o  -> output channel 1+o
                        stg[px * SP2 + o] = acc[mt][nt][j] + __ldg(&cb[o]);
                    } else if (o <= 64) {
                        // stage col 0 = obj (ch 0); cols 1..64 = reg (ch 81..144)
                        float bias = (o < 64) ? __ldg(&rb[o]) : __ldg(ob);
                        int ch = (o < 64) ? (1 + o) : 0;
                        stg[px * SP2 + ch] = acc[mt][nt][j] + bias;
                    }
                }
    }
    __syncthreads();

    if (flavor) {
        // DFL decode + box: 512 tasks, 2 per thread; max-free softmax (bounded logits)
        #pragma unroll
        for (int it = 0; it < 2; it++) {
            int task = t + it * 256;
            int m = task >> 2, f = task & 3;
            const float* row = &stg[m * SP2 + 1 + 16 * f];
            float se = 0.f, sw = 0.f;
            #pragma unroll
            for (int i = 0; i < 16; i++) {
                float ev = __expf(row[i]);
                se += ev;
                sw = fmaf(ev, (float)i, sw);
            }
            float d = (sw / se) * (16.0f / 15.0f);   // proj[i] = i * 16/15
            int mg = m0 + m;
            int hh = mg / W, ww = mg - hh * W;
            float ax = ((float)ww + 0.5f) * stride;
            float ay = ((float)hh + 0.5f) * stride;
            float ds = d * stride;
            float v = (f == 0) ? (ax - ds) : (f == 1) ? (ay - ds)
                    : (f == 2) ? (ax + ds) : (ay + ds);
            stg[m * SP2 + 65 + f] = v;   // box -> stage cols 65..68 (ch 145..148)
        }
        __syncthreads();
    }

    // flavor-specific coalesced store (byte-disjoint channel ranges per row)
    {
        float* outp = out + ((size_t)b * 8400 + moff + m0) * 149;
        if (flavor == 0) {
            for (int m = wid; m < mvalid; m += 8) {
                const float* srow = stg + m * SP2;
                float* drow = outp + m * 149 + 1;          // channels 1..80
                #pragma unroll
                for (int c2 = lane; c2 < 80; c2 += 32)
                    drow[c2] = srow[c2];
            }
        } else {
            for (int m = wid; m < mvalid; m += 8) {
                const float* srow = stg + m * SP2;
                float* drow = outp + m * 149;
                if (lane == 0) drow[0] = srow[0];          // obj
                #pragma unroll
                for (int c2 = lane; c2 < 68; c2 += 32)     // reg 81..144 + box 145..148
                    drow[81 + c2] = srow[1 + c2];
            }
        }
    }
}

extern "C" void kernel_launch(void* const* d_in, const int* in_sizes, int n_in,
                              void* d_out, int out_size)
{
    Params P;
    if (in_sizes[1] == in_sizes[0]) {       // dict order cls0,reg0,cls1,reg1,cls2,reg2
        P.clsF[0] = (const float*)d_in[0]; P.regF[0] = (const float*)d_in[1];
        P.clsF[1] = (const float*)d_in[2]; P.regF[1] = (const float*)d_in[3];
        P.clsF[2] = (const float*)d_in[4]; P.regF[2] = (const float*)d_in[5];
    } else {                                // signature order cls0,cls1,cls2,reg0,reg1,reg2
        P.clsF[0] = (const float*)d_in[0]; P.regF[0] = (const float*)d_in[3];
        P.clsF[1] = (const float*)d_in[1]; P.regF[1] = (const float*)d_in[4];
        P.clsF[2] = (const float*)d_in[2]; P.regF[2] = (const float*)d_in[5];
    }
    for (int l = 0; l < 3; l++) {
        P.ow[l] = (const float*)d_in[6  + 6 * l];
        P.ob[l] = (const float*)d_in[7  + 6 * l];
        P.cw[l] = (const float*)d_in[8  + 6 * l];
        P.cb[l] = (const float*)d_in[9  + 6 * l];
        P.rw[l] = (const float*)d_in[10 + 6 * l];
        P.rb[l] = (const float*)d_in[11 + 6 * l];
    }
    int B = in_sizes[0] / (256 * 6400);

    static int configured = 0;
    if (!configured) {
        cudaFuncSetAttribute(pred_tf32_kernel, cudaFuncAttributeMaxDynamicSharedMemorySize, SMEM_TOTAL);
        configured = 1;
    }
    dim3 grid(67, B, 2);                    // (50+13+4 tiles) x batch x 2 GEMM flavors
    pred_tf32_kernel<<<grid, 256, SMEM_TOTAL>>>(P, (float*)d_out);
}